// round 14
// baseline (speedup 1.0000x reference)
#include <cuda_runtime.h>
#include <cuda_bf16.h>
#include <cstdint>

#define NN 8192
#define IND 512
#define HID 256
#define OUTD 64
#define NC 80       // Wt cols: G[0:64], s1=64, s2=65, pad to 80
#define NJT 16      // j-tiles of 128 per CTA (split-j: 4 quarters)
#define PROW 68     // partial row stride (floats): 64 cols + Z + pad

// ---------------- scratch ----------------
__device__ __nv_bfloat16 g_Wt[1024 * NC];   // split W-tilde, chunk-interleaved rows
__device__ float g_bc[66];
__device__ __nv_bfloat16 g_Gb[NN * OUTD];   // G = H1@Omega + b, bf16 row-major (L2-resident)
__device__ float g_s1[NN], g_s2[NN];
__device__ uint32_t g_up[NN], g_up2[NN];    // u_i / u2_i duplicated bf16x2
__device__ uint32_t g_vp[NN / 2], g_vp2[NN / 2];
__device__ float g_Part[4 * NN * PROW];     // split-j partials [jq][row][68]

// ---------------- mma helpers ----------------
__device__ __forceinline__ void ldsm4(uint32_t& r0, uint32_t& r1, uint32_t& r2, uint32_t& r3,
                                      const void* p) {
    uint32_t ad = (uint32_t)__cvta_generic_to_shared(p);
    asm volatile("ldmatrix.sync.aligned.m8n8.x4.shared.b16 {%0,%1,%2,%3}, [%4];"
                 : "=r"(r0), "=r"(r1), "=r"(r2), "=r"(r3) : "r"(ad));
}
__device__ __forceinline__ void ldsm4t(uint32_t& r0, uint32_t& r1, uint32_t& r2, uint32_t& r3,
                                       const void* p) {
    uint32_t ad = (uint32_t)__cvta_generic_to_shared(p);
    asm volatile("ldmatrix.sync.aligned.m8n8.x4.trans.shared.b16 {%0,%1,%2,%3}, [%4];"
                 : "=r"(r0), "=r"(r1), "=r"(r2), "=r"(r3) : "r"(ad));
}
__device__ __forceinline__ void mma16816(float* c, uint32_t a0, uint32_t a1, uint32_t a2,
                                         uint32_t a3, uint32_t b0, uint32_t b1) {
    asm volatile(
        "mma.sync.aligned.m16n8k16.row.col.f32.bf16.bf16.f32 "
        "{%0,%1,%2,%3}, {%4,%5,%6,%7}, {%8,%9}, {%0,%1,%2,%3};"
        : "+f"(c[0]), "+f"(c[1]), "+f"(c[2]), "+f"(c[3])
        : "r"(a0), "r"(a1), "r"(a2), "r"(a3), "r"(b0), "r"(b1));
}
__device__ __forceinline__ __nv_bfloat162 asb2(uint32_t x) {
    return *reinterpret_cast<__nv_bfloat162*>(&x);
}
__device__ __forceinline__ uint32_t asu32(__nv_bfloat162 x) {
    return *reinterpret_cast<uint32_t*>(&x);
}

// ---------------- k_prep: W~ = [W1@Omega | W1@a1 | W1@a2], chunk-interleaved split rows ----
__global__ void k_prep(const float* __restrict__ W1, const float* __restrict__ b1,
                       const float* __restrict__ a, const float* __restrict__ Omega) {
    __shared__ float wrow[HID];
    int blk = blockIdx.x;   // 0..511: W1 row; 512: b1
    int tid = threadIdx.x;
    const float* src = (blk < IND) ? (W1 + blk * HID) : b1;
    for (int k = tid; k < HID; k += 128) wrow[k] = src[k];
    __syncthreads();
    if (tid >= NC) return;
    float val = 0.f;
    if (tid < 64) {
        for (int k = 0; k < HID; k++) val += wrow[k] * Omega[k * OUTD + tid];
    } else if (tid == 64) {
        for (int k = 0; k < HID; k++) val += wrow[k] * a[k];
    } else if (tid == 65) {
        for (int k = 0; k < HID; k++) val += wrow[k] * a[HID + k];
    }
    if (blk < IND) {
        __nv_bfloat16 hi = __float2bfloat16(val);
        float lo = val - __bfloat162float(hi);
        int rhi = ((blk >> 5) << 6) + (blk & 31);
        g_Wt[rhi * NC + tid] = hi;
        g_Wt[(rhi + 32) * NC + tid] = __float2bfloat16(lo);
    } else if (tid < 66) {
        g_bc[tid] = val;
    }
}

// ---------------- k_sg: [G | s1 | s2] = split(X) @ Wt, inline fp32->bf16 hi/lo split ------
__global__ __launch_bounds__(256) void k_sg(const float* __restrict__ X) {
    __shared__ __align__(16) __nv_bfloat16 aT[64][72];   // 64 rows x (32 hi | 32 lo)
    __shared__ __align__(16) __nv_bfloat16 bT[64][88];
    int tid = threadIdx.x, lane = tid & 31, w = tid >> 5;
    int m0 = blockIdx.x * 64;
    int mi = (w >> 1) * 16;
    int cw = w & 1;   // 0: nt 0..2 (cols 0-47), 1: nt 3..4 (cols 48-79)
    float acc[6][4];
#pragma unroll
    for (int i = 0; i < 6; i++)
#pragma unroll
        for (int j = 0; j < 4; j++) acc[i][j] = 0.f;

    for (int ch = 0; ch < 16; ch++) {
#pragma unroll
        for (int q = 0; q < 2; q++) {
            int idx = q * 256 + tid;          // 512 float4
            int rr = idx >> 3, c4 = (idx & 7) * 4;
            float4 xv = *(const float4*)&X[(m0 + rr) * IND + ch * 32 + c4];
            __nv_bfloat162 h0 = __floats2bfloat162_rn(xv.x, xv.y);
            __nv_bfloat162 h1 = __floats2bfloat162_rn(xv.z, xv.w);
            __nv_bfloat162 l0 = __floats2bfloat162_rn(xv.x - __bfloat162float(__low2bfloat16(h0)),
                                                      xv.y - __bfloat162float(__high2bfloat16(h0)));
            __nv_bfloat162 l1 = __floats2bfloat162_rn(xv.z - __bfloat162float(__low2bfloat16(h1)),
                                                      xv.w - __bfloat162float(__high2bfloat16(h1)));
            *(uint2*)&aT[rr][c4] = make_uint2(asu32(h0), asu32(h1));
            *(uint2*)&aT[rr][32 + c4] = make_uint2(asu32(l0), asu32(l1));
        }
#pragma unroll
        for (int q = 0; q < 3; q++) {
            int idx = q * 256 + tid;
            if (idx < 640) {
                int rr = idx / 10, cc = idx % 10;
                *(uint4*)&bT[rr][cc * 8] = *(const uint4*)&g_Wt[(ch * 64 + rr) * NC + cc * 8];
            }
        }
        __syncthreads();
        int g = lane >> 3;
        int r = (lane & 7) + (g & 1) * 8;
        int c = (g >> 1) * 8;
#pragma unroll
        for (int ks = 0; ks < 64; ks += 16) {
            uint32_t a0, a1, a2, a3;
            ldsm4(a0, a1, a2, a3, &aT[mi + r][ks + c]);
            if (cw == 0) {
#pragma unroll
                for (int nt = 0; nt < 3; nt++) {
                    uint32_t b0, b1r, b2, b3;
                    ldsm4t(b0, b1r, b2, b3, &bT[ks + r][nt * 16 + c]);
                    mma16816(acc[nt * 2], a0, a1, a2, a3, b0, b1r);
                    mma16816(acc[nt * 2 + 1], a0, a1, a2, a3, b2, b3);
                }
            } else {
#pragma unroll
                for (int nt2 = 0; nt2 < 2; nt2++) {
                    uint32_t b0, b1r, b2, b3;
                    ldsm4t(b0, b1r, b2, b3, &bT[ks + r][(nt2 + 3) * 16 + c]);
                    mma16816(acc[nt2 * 2], a0, a1, a2, a3, b0, b1r);
                    mma16816(acc[nt2 * 2 + 1], a0, a1, a2, a3, b2, b3);
                }
            }
        }
        __syncthreads();
    }
    int r0 = m0 + mi + (lane >> 2);
    if (cw == 0) {
#pragma unroll
        for (int nt = 0; nt < 3; nt++)
#pragma unroll
            for (int h = 0; h < 2; h++) {
                int j = nt * 2 + h;
                int cb = nt * 16 + h * 8 + (lane & 3) * 2;
                float b0v = g_bc[cb], b1v = g_bc[cb + 1];
                __nv_bfloat162 p0 = __floats2bfloat162_rn(acc[j][0] + b0v, acc[j][1] + b1v);
                __nv_bfloat162 p1 = __floats2bfloat162_rn(acc[j][2] + b0v, acc[j][3] + b1v);
                *(uint32_t*)&g_Gb[r0 * OUTD + cb] = asu32(p0);
                *(uint32_t*)&g_Gb[(r0 + 8) * OUTD + cb] = asu32(p1);
            }
    } else {
#pragma unroll
        for (int h = 0; h < 2; h++) {
            int cb = 48 + h * 8 + (lane & 3) * 2;
            float b0v = g_bc[cb], b1v = g_bc[cb + 1];
            __nv_bfloat162 p0 = __floats2bfloat162_rn(acc[h][0] + b0v, acc[h][1] + b1v);
            __nv_bfloat162 p1 = __floats2bfloat162_rn(acc[h][2] + b0v, acc[h][3] + b1v);
            *(uint32_t*)&g_Gb[r0 * OUTD + cb] = asu32(p0);
            *(uint32_t*)&g_Gb[(r0 + 8) * OUTD + cb] = asu32(p1);
        }
        if ((lane & 3) == 0) {
            g_s1[r0] = acc[2][0] + g_bc[64];
            g_s2[r0] = acc[2][1] + g_bc[65];
            g_s1[r0 + 8] = acc[2][2] + g_bc[64];
            g_s2[r0 + 8] = acc[2][3] + g_bc[65];
        }
    }
}

// ---------------- k_maxuv: single-CTA max(s2) + u/v factor packing ----------------
__global__ __launch_bounds__(1024) void k_maxuv() {
    __shared__ float red[32];
    int tid = threadIdx.x, lane = tid & 31;
    float m = -1e30f;
    for (int i = tid; i < NN; i += 1024) m = fmaxf(m, g_s2[i]);
#pragma unroll
    for (int o = 16; o; o >>= 1) m = fmaxf(m, __shfl_xor_sync(0xffffffffu, m, o));
    if (lane == 0) red[tid >> 5] = m;
    __syncthreads();
    if (tid < 32) {
        float x = red[tid];
#pragma unroll
        for (int o = 16; o; o >>= 1) x = fmaxf(x, __shfl_xor_sync(0xffffffffu, x, o));
        if (tid == 0) red[0] = x;
    }
    __syncthreads();
    float M = red[0];
    for (int i = tid; i < NN; i += 1024) {
        float s1 = g_s1[i], s2 = g_s2[i];
        float t = s1 + M;
        float c = t > 0.f ? t : 0.2f * t;   // valid softmax shift (leaky_relu monotone)
        uint32_t ub = (uint32_t)__bfloat16_as_ushort(__float2bfloat16(expf(s1 - c)));
        g_up[i] = ub | (ub << 16);
        uint32_t u2b = (uint32_t)__bfloat16_as_ushort(__float2bfloat16(expf(0.2f * s1 - c)));
        g_up2[i] = u2b | (u2b << 16);
        if (i < NN / 2) {
            float sa = g_s2[2 * i], sb = g_s2[2 * i + 1];
            uint32_t v0 = (uint32_t)__bfloat16_as_ushort(__float2bfloat16(expf(sa)));
            uint32_t v1 = (uint32_t)__bfloat16_as_ushort(__float2bfloat16(expf(sb)));
            g_vp[i] = v0 | (v1 << 16);
            uint32_t w0 = (uint32_t)__bfloat16_as_ushort(__float2bfloat16(expf(0.2f * sa)));
            uint32_t w1 = (uint32_t)__bfloat16_as_ushort(__float2bfloat16(expf(0.2f * sb)));
            g_vp2[i] = w0 | (w1 << 16);
        }
    }
}

// ---------------- k_pv: partials = P@[G|1], M=64 i-tiles x j-quarters ----------------
// smem: gT[2][128][72] bf16 (double buffer), pT[64][136] bf16 (single buffer)
#define GT_STRIDE 18432                     // 128*144 B
#define OFF_GT 0                            // 2 * 18432 = 36864
#define OFF_PT 36864                        // 64*272 = 17408
#define SMEM_PV 54272

__device__ __forceinline__ void pv_load_gt(uint32_t sm, int buf, int j0, int tid) {
    uint32_t dbase = sm + OFF_GT + buf * GT_STRIDE;
    const char* src = (const char*)(g_Gb + (size_t)j0 * OUTD);
#pragma unroll
    for (int q = 0; q < 4; q++) {
        int idx = q * 256 + tid;
        int r = idx >> 3, cc = idx & 7;
        asm volatile("cp.async.cg.shared.global [%0], [%1], 16;" ::"r"(dbase + r * 144 + cc * 16),
                     "l"(src + r * 128 + cc * 16));
    }
    asm volatile("cp.async.commit_group;" ::: "memory");
}

__global__ __launch_bounds__(256, 4) void k_pv(const int* __restrict__ A) {
    extern __shared__ __align__(16) char smem[];
    uint32_t sm = (uint32_t)__cvta_generic_to_shared(smem);
    int tid = threadIdx.x, lane = tid & 31, wid = tid >> 5;
    int i0 = (blockIdx.x >> 2) * 64;
    int jq = blockIdx.x & 3;
    int jbase = jq * 2048;
    int mi = (wid >> 1) * 16, nb = (wid & 1) * 32;
    int il = tid >> 2, jc = tid & 3;        // build: row il (0..63), 32 j per thread
    const int* arow = A + (long)(i0 + il) * NN + jbase + jc * 32;
    __nv_bfloat162 UX = asb2(g_up[i0 + il]);
    __nv_bfloat162 UX2 = asb2(g_up2[i0 + il]);

    float acc[4][4], accz[4];
#pragma unroll
    for (int nt = 0; nt < 4; nt++)
#pragma unroll
        for (int j = 0; j < 4; j++) acc[nt][j] = 0.f;
#pragma unroll
    for (int j = 0; j < 4; j++) accz[j] = 0.f;

    pv_load_gt(sm, 0, jbase, tid);

    const uint32_t ONES = 0x3F803F80u;
    int g = lane >> 3;
    int r = (lane & 7) + (g & 1) * 8;
    int c = (g >> 1) * 8;
    char* pdst = smem + OFF_PT + il * 272 + jc * 64;

    for (int jt = 0; jt < NJT; jt++) {
        // ---- build phase: pT[64][128] for this jt ----
        const uint4* ap = (const uint4*)(arow + (long)jt * 128);
        int vidx = ((jbase + jt * 128) >> 1) + jc * 16;
        const uint4* vp = (const uint4*)(g_vp + vidx);
        const uint4* wp = (const uint4*)(g_vp2 + vidx);
#pragma unroll
        for (int h = 0; h < 2; h++) {
            uint4 A0 = __ldcs(ap + h * 4), A1 = __ldcs(ap + h * 4 + 1);
            uint4 A2 = __ldcs(ap + h * 4 + 2), A3 = __ldcs(ap + h * 4 + 3);
            uint4 vv0 = __ldg(vp + h * 2), vv1 = __ldg(vp + h * 2 + 1);
            uint4 ww0 = __ldg(wp + h * 2), ww1 = __ldg(wp + h * 2 + 1);
            uint32_t po[8], m;
#define PV_PAIR(dst, a0v, a1v, vv, ww)                                                   \
    m = __byte_perm((uint32_t)(a0v), (uint32_t)(a1v), 0x5410) * 0x3F80u;                 \
    dst = asu32(__hmul2(__hmax2(__hmul2(UX, asb2(vv)), __hmul2(UX2, asb2(ww))), asb2(m)));
            PV_PAIR(po[0], A0.x, A0.y, vv0.x, ww0.x)
            PV_PAIR(po[1], A0.z, A0.w, vv0.y, ww0.y)
            PV_PAIR(po[2], A1.x, A1.y, vv0.z, ww0.z)
            PV_PAIR(po[3], A1.z, A1.w, vv0.w, ww0.w)
            PV_PAIR(po[4], A2.x, A2.y, vv1.x, ww1.x)
            PV_PAIR(po[5], A2.z, A2.w, vv1.y, ww1.y)
            PV_PAIR(po[6], A3.x, A3.y, vv1.z, ww1.z)
            PV_PAIR(po[7], A3.z, A3.w, vv1.w, ww1.w)
#undef PV_PAIR
            *(uint4*)(pdst + h * 32) = make_uint4(po[0], po[1], po[2], po[3]);
            *(uint4*)(pdst + h * 32 + 16) = make_uint4(po[4], po[5], po[6], po[7]);
        }
        // L2 prefetch next jt's A line (each thread's 32 ints = one 128B line)
        if (jt < NJT - 1)
            asm volatile("prefetch.global.L2 [%0];" ::"l"(arow + (long)(jt + 1) * 128));
        __syncthreads();

        // ---- mma phase ----
        if (jt < NJT - 1) {
            pv_load_gt(sm, (jt + 1) & 1, jbase + ((jt + 1) << 7), tid);
            asm volatile("cp.async.wait_group 1;" ::: "memory");
        } else {
            asm volatile("cp.async.wait_group 0;" ::: "memory");
        }
        const char* pb = smem + OFF_PT;
        const char* hb = smem + OFF_GT + (jt & 1) * GT_STRIDE;
#pragma unroll
        for (int ks = 0; ks < 8; ks++) {
            uint32_t a0, a1, a2, a3;
            ldsm4(a0, a1, a2, a3, pb + (mi + r) * 272 + (ks * 16 + c) * 2);
            if ((wid & 1) == 0) mma16816(accz, a0, a1, a2, a3, ONES, ONES);
            uint32_t b0, b1r, b2, b3;
            ldsm4t(b0, b1r, b2, b3, hb + (ks * 16 + r) * 144 + (nb + c) * 2);
            mma16816(acc[0], a0, a1, a2, a3, b0, b1r);
            mma16816(acc[1], a0, a1, a2, a3, b2, b3);
            uint32_t c0, c1r, c2, c3;
            ldsm4t(c0, c1r, c2, c3, hb + (ks * 16 + r) * 144 + (nb + 16 + c) * 2);
            mma16816(acc[2], a0, a1, a2, a3, c0, c1r);
            mma16816(acc[3], a0, a1, a2, a3, c2, c3);
        }
        __syncthreads();   // pT free for rebuild; gT[jt&1] free for reuse at jt+2
    }

    // ---- write fp32 partials ----
    int r0 = mi + (lane >> 2);
    float* P0 = g_Part + ((size_t)jq * NN + (i0 + r0)) * PROW;
    float* P1 = P0 + 8 * PROW;
#pragma unroll
    for (int nt = 0; nt < 4; nt++) {
        int cb = nb + nt * 8 + (lane & 3) * 2;
        P0[cb] = acc[nt][0];
        P0[cb + 1] = acc[nt][1];
        P1[cb] = acc[nt][2];
        P1[cb + 1] = acc[nt][3];
    }
    if (((wid & 1) == 0) && ((lane & 3) == 0)) {
        P0[64] = accz[0];
        P1[64] = accz[2];
    }
}

// ---------------- k_fin: combine 4 split-j partials + sigmoid ----------------
__global__ void k_fin(const float* __restrict__ beta, float* __restrict__ out) {
    int idx = blockIdx.x * 256 + threadIdx.x;
    if (idx >= NN * OUTD) return;
    int rr = idx >> 6, cc = idx & 63;
    float n = 0.f, z = 0.f;
#pragma unroll
    for (int q = 0; q < 4; q++) {
        const float* p = g_Part + ((size_t)q * NN + rr) * PROW;
        n += p[cc];
        z += p[64];
    }
    out[idx] = 1.f / (1.f + expf(-(n / z + beta[cc])));
}

// ---------------- launch: k_pv at profiled index 3 ----------------
extern "C" void kernel_launch(void* const* d_in, const int* in_sizes, int n_in,
                              void* d_out, int out_size) {
    const float* X = (const float*)d_in[0];
    const int* A = (const int*)d_in[1];
    const float* W1 = (const float*)d_in[2];
    const float* b1 = (const float*)d_in[3];
    const float* a = (const float*)d_in[4];
    const float* Omega = (const float*)d_in[5];
    const float* beta = (const float*)d_in[6];
    float* out = (float*)d_out;

    cudaFuncSetAttribute(k_pv, cudaFuncAttributeMaxDynamicSharedMemorySize, SMEM_PV);

    k_prep<<<IND + 1, 128>>>(W1, b1, a, Omega);
    k_sg<<<NN / 64, 256>>>(X);
    k_maxuv<<<1, 1024>>>();
    k_pv<<<(NN / 64) * 4, 256, SMEM_PV>>>(A);
    k_fin<<<(NN * OUTD + 255) / 256, 256>>>(beta, out);
}

// round 15
// speedup vs baseline: 1.1796x; 1.1796x over previous
#include <cuda_runtime.h>
#include <cuda_bf16.h>
#include <cstdint>

#define NN 8192
#define IND 512
#define HID 256
#define OUTD 64
#define NC 80       // Wt cols: G[0:64], s1=64, s2=65, pad to 80
#define NJT 16      // j-tiles of 128 per CTA (split-j: 4 quarters of 2048)
#define PROW 68     // partial row stride (floats): 64 cols + Z + pad

// ---------------- scratch ----------------
__device__ __nv_bfloat16 g_Wt[1024 * NC];   // split W-tilde, chunk-interleaved rows
__device__ float g_bc[66];
__device__ __nv_bfloat16 g_Gb[NN * OUTD];   // G = H1@Omega + b, bf16 row-major (L2-resident)
__device__ float g_s1[NN], g_s2[NN];
__device__ uint32_t g_up[NN], g_up2[NN];    // u_i / u2_i duplicated bf16x2
__device__ uint32_t g_vp[NN / 2], g_vp2[NN / 2];
__device__ float g_Part[4 * NN * PROW];     // split-j partials [jq][row][68]

// ---------------- mma helpers ----------------
__device__ __forceinline__ void ldsm4(uint32_t& r0, uint32_t& r1, uint32_t& r2, uint32_t& r3,
                                      const void* p) {
    uint32_t ad = (uint32_t)__cvta_generic_to_shared(p);
    asm volatile("ldmatrix.sync.aligned.m8n8.x4.shared.b16 {%0,%1,%2,%3}, [%4];"
                 : "=r"(r0), "=r"(r1), "=r"(r2), "=r"(r3) : "r"(ad));
}
__device__ __forceinline__ void ldsm4t(uint32_t& r0, uint32_t& r1, uint32_t& r2, uint32_t& r3,
                                       const void* p) {
    uint32_t ad = (uint32_t)__cvta_generic_to_shared(p);
    asm volatile("ldmatrix.sync.aligned.m8n8.x4.trans.shared.b16 {%0,%1,%2,%3}, [%4];"
                 : "=r"(r0), "=r"(r1), "=r"(r2), "=r"(r3) : "r"(ad));
}
__device__ __forceinline__ void mma16816(float* c, uint32_t a0, uint32_t a1, uint32_t a2,
                                         uint32_t a3, uint32_t b0, uint32_t b1) {
    asm volatile(
        "mma.sync.aligned.m16n8k16.row.col.f32.bf16.bf16.f32 "
        "{%0,%1,%2,%3}, {%4,%5,%6,%7}, {%8,%9}, {%0,%1,%2,%3};"
        : "+f"(c[0]), "+f"(c[1]), "+f"(c[2]), "+f"(c[3])
        : "r"(a0), "r"(a1), "r"(a2), "r"(a3), "r"(b0), "r"(b1));
}
__device__ __forceinline__ __nv_bfloat162 asb2(uint32_t x) {
    return *reinterpret_cast<__nv_bfloat162*>(&x);
}
__device__ __forceinline__ uint32_t asu32(__nv_bfloat162 x) {
    return *reinterpret_cast<uint32_t*>(&x);
}

// ---------------- k_prep: W~ = [W1@Omega | W1@a1 | W1@a2], chunk-interleaved split rows ----
__global__ void k_prep(const float* __restrict__ W1, const float* __restrict__ b1,
                       const float* __restrict__ a, const float* __restrict__ Omega) {
    __shared__ float wrow[HID];
    int blk = blockIdx.x;   // 0..511: W1 row; 512: b1
    int tid = threadIdx.x;
    const float* src = (blk < IND) ? (W1 + blk * HID) : b1;
    for (int k = tid; k < HID; k += 128) wrow[k] = src[k];
    __syncthreads();
    if (tid >= NC) return;
    float val = 0.f;
    if (tid < 64) {
        for (int k = 0; k < HID; k++) val += wrow[k] * Omega[k * OUTD + tid];
    } else if (tid == 64) {
        for (int k = 0; k < HID; k++) val += wrow[k] * a[k];
    } else if (tid == 65) {
        for (int k = 0; k < HID; k++) val += wrow[k] * a[HID + k];
    }
    if (blk < IND) {
        __nv_bfloat16 hi = __float2bfloat16(val);
        float lo = val - __bfloat162float(hi);
        int rhi = ((blk >> 5) << 6) + (blk & 31);
        g_Wt[rhi * NC + tid] = hi;
        g_Wt[(rhi + 32) * NC + tid] = __float2bfloat16(lo);
    } else if (tid < 66) {
        g_bc[tid] = val;
    }
}

// ---------------- k_sg: [G | s1 | s2] = split(X) @ Wt, inline fp32->bf16 hi/lo split ------
__global__ __launch_bounds__(256) void k_sg(const float* __restrict__ X) {
    __shared__ __align__(16) __nv_bfloat16 aT[64][72];   // 64 rows x (32 hi | 32 lo)
    __shared__ __align__(16) __nv_bfloat16 bT[64][88];
    int tid = threadIdx.x, lane = tid & 31, w = tid >> 5;
    int m0 = blockIdx.x * 64;
    int mi = (w >> 1) * 16;
    int cw = w & 1;   // 0: nt 0..2 (cols 0-47), 1: nt 3..4 (cols 48-79)
    float acc[6][4];
#pragma unroll
    for (int i = 0; i < 6; i++)
#pragma unroll
        for (int j = 0; j < 4; j++) acc[i][j] = 0.f;

    for (int ch = 0; ch < 16; ch++) {
#pragma unroll
        for (int q = 0; q < 2; q++) {
            int idx = q * 256 + tid;          // 512 float4
            int rr = idx >> 3, c4 = (idx & 7) * 4;
            float4 xv = *(const float4*)&X[(m0 + rr) * IND + ch * 32 + c4];
            __nv_bfloat162 h0 = __floats2bfloat162_rn(xv.x, xv.y);
            __nv_bfloat162 h1 = __floats2bfloat162_rn(xv.z, xv.w);
            __nv_bfloat162 l0 = __floats2bfloat162_rn(xv.x - __bfloat162float(__low2bfloat16(h0)),
                                                      xv.y - __bfloat162float(__high2bfloat16(h0)));
            __nv_bfloat162 l1 = __floats2bfloat162_rn(xv.z - __bfloat162float(__low2bfloat16(h1)),
                                                      xv.w - __bfloat162float(__high2bfloat16(h1)));
            *(uint2*)&aT[rr][c4] = make_uint2(asu32(h0), asu32(h1));
            *(uint2*)&aT[rr][32 + c4] = make_uint2(asu32(l0), asu32(l1));
        }
#pragma unroll
        for (int q = 0; q < 3; q++) {
            int idx = q * 256 + tid;
            if (idx < 640) {
                int rr = idx / 10, cc = idx % 10;
                *(uint4*)&bT[rr][cc * 8] = *(const uint4*)&g_Wt[(ch * 64 + rr) * NC + cc * 8];
            }
        }
        __syncthreads();
        int g = lane >> 3;
        int r = (lane & 7) + (g & 1) * 8;
        int c = (g >> 1) * 8;
#pragma unroll
        for (int ks = 0; ks < 64; ks += 16) {
            uint32_t a0, a1, a2, a3;
            ldsm4(a0, a1, a2, a3, &aT[mi + r][ks + c]);
            if (cw == 0) {
#pragma unroll
                for (int nt = 0; nt < 3; nt++) {
                    uint32_t b0, b1r, b2, b3;
                    ldsm4t(b0, b1r, b2, b3, &bT[ks + r][nt * 16 + c]);
                    mma16816(acc[nt * 2], a0, a1, a2, a3, b0, b1r);
                    mma16816(acc[nt * 2 + 1], a0, a1, a2, a3, b2, b3);
                }
            } else {
#pragma unroll
                for (int nt2 = 0; nt2 < 2; nt2++) {
                    uint32_t b0, b1r, b2, b3;
                    ldsm4t(b0, b1r, b2, b3, &bT[ks + r][(nt2 + 3) * 16 + c]);
                    mma16816(acc[nt2 * 2], a0, a1, a2, a3, b0, b1r);
                    mma16816(acc[nt2 * 2 + 1], a0, a1, a2, a3, b2, b3);
                }
            }
        }
        __syncthreads();
    }
    int r0 = m0 + mi + (lane >> 2);
    if (cw == 0) {
#pragma unroll
        for (int nt = 0; nt < 3; nt++)
#pragma unroll
            for (int h = 0; h < 2; h++) {
                int j = nt * 2 + h;
                int cb = nt * 16 + h * 8 + (lane & 3) * 2;
                float b0v = g_bc[cb], b1v = g_bc[cb + 1];
                __nv_bfloat162 p0 = __floats2bfloat162_rn(acc[j][0] + b0v, acc[j][1] + b1v);
                __nv_bfloat162 p1 = __floats2bfloat162_rn(acc[j][2] + b0v, acc[j][3] + b1v);
                *(uint32_t*)&g_Gb[r0 * OUTD + cb] = asu32(p0);
                *(uint32_t*)&g_Gb[(r0 + 8) * OUTD + cb] = asu32(p1);
            }
    } else {
#pragma unroll
        for (int h = 0; h < 2; h++) {
            int cb = 48 + h * 8 + (lane & 3) * 2;
            float b0v = g_bc[cb], b1v = g_bc[cb + 1];
            __nv_bfloat162 p0 = __floats2bfloat162_rn(acc[h][0] + b0v, acc[h][1] + b1v);
            __nv_bfloat162 p1 = __floats2bfloat162_rn(acc[h][2] + b0v, acc[h][3] + b1v);
            *(uint32_t*)&g_Gb[r0 * OUTD + cb] = asu32(p0);
            *(uint32_t*)&g_Gb[(r0 + 8) * OUTD + cb] = asu32(p1);
        }
        if ((lane & 3) == 0) {
            g_s1[r0] = acc[2][0] + g_bc[64];
            g_s2[r0] = acc[2][1] + g_bc[65];
            g_s1[r0 + 8] = acc[2][2] + g_bc[64];
            g_s2[r0 + 8] = acc[2][3] + g_bc[65];
        }
    }
}

// ---------------- k_maxuv: single-CTA max(s2) + u/v factor packing ----------------
__global__ __launch_bounds__(1024) void k_maxuv() {
    __shared__ float red[32];
    int tid = threadIdx.x, lane = tid & 31;
    float m = -1e30f;
    for (int i = tid; i < NN; i += 1024) m = fmaxf(m, g_s2[i]);
#pragma unroll
    for (int o = 16; o; o >>= 1) m = fmaxf(m, __shfl_xor_sync(0xffffffffu, m, o));
    if (lane == 0) red[tid >> 5] = m;
    __syncthreads();
    if (tid < 32) {
        float x = red[tid];
#pragma unroll
        for (int o = 16; o; o >>= 1) x = fmaxf(x, __shfl_xor_sync(0xffffffffu, x, o));
        if (tid == 0) red[0] = x;
    }
    __syncthreads();
    float M = red[0];
    for (int i = tid; i < NN; i += 1024) {
        float s1 = g_s1[i], s2 = g_s2[i];
        float t = s1 + M;
        float c = t > 0.f ? t : 0.2f * t;   // valid softmax shift (leaky_relu monotone)
        uint32_t ub = (uint32_t)__bfloat16_as_ushort(__float2bfloat16(expf(s1 - c)));
        g_up[i] = ub | (ub << 16);
        uint32_t u2b = (uint32_t)__bfloat16_as_ushort(__float2bfloat16(expf(0.2f * s1 - c)));
        g_up2[i] = u2b | (u2b << 16);
        if (i < NN / 2) {
            float sa = g_s2[2 * i], sb = g_s2[2 * i + 1];
            uint32_t v0 = (uint32_t)__bfloat16_as_ushort(__float2bfloat16(expf(sa)));
            uint32_t v1 = (uint32_t)__bfloat16_as_ushort(__float2bfloat16(expf(sb)));
            g_vp[i] = v0 | (v1 << 16);
            uint32_t w0 = (uint32_t)__bfloat16_as_ushort(__float2bfloat16(expf(0.2f * sa)));
            uint32_t w1 = (uint32_t)__bfloat16_as_ushort(__float2bfloat16(expf(0.2f * sb)));
            g_vp2[i] = w0 | (w1 << 16);
        }
    }
}

// ---------------- k_pv: partials = P@G (+build-side Z), 1024 CTAs, R13 pipeline ----------
// smem: gT[2][128][72] bf16 (cp.async double buffer), pT[2][32][136] bf16
#define GT_STRIDE 18432                     // 128*144 B
#define OFF_GT 0                            // 2 * 18432 = 36864
#define OFF_PT 36864                        // 2 * 8704 = 17408
#define PT_STRIDE 8704                      // 32*272 B
#define SMEM_PV 54272

__device__ __forceinline__ void pv_load_gt(uint32_t sm, int buf, int j0, int tid) {
    uint32_t dbase = sm + OFF_GT + buf * GT_STRIDE;
    const char* src = (const char*)(g_Gb + (size_t)j0 * OUTD);
#pragma unroll
    for (int q = 0; q < 4; q++) {
        int idx = q * 256 + tid;
        int r = idx >> 3, cc = idx & 7;
        asm volatile("cp.async.cg.shared.global [%0], [%1], 16;" ::"r"(dbase + r * 144 + cc * 16),
                     "l"(src + r * 128 + cc * 16));
    }
    asm volatile("cp.async.commit_group;" ::: "memory");
}

// builds the 16 p-values for (row il, j-chunk jc) of tile at global offset j0;
// returns this thread's fp32 sum of those p-values (for Z).
__device__ __forceinline__ float pv_build(char* smem, int buf, int j0, const int4* Ac,
                                          __nv_bfloat162 UX, __nv_bfloat162 UX2, int il, int jc) {
    const uint4* vp = (const uint4*)(g_vp + (j0 >> 1) + (jc << 3));
    uint4 vA = __ldg(vp), vB = __ldg(vp + 1);
    const uint4* wp = (const uint4*)(g_vp2 + (j0 >> 1) + (jc << 3));
    uint4 wA = __ldg(wp), wB = __ldg(wp + 1);
    uint32_t po[8];
    uint32_t m;
#define PV_PAIR(dst, a0v, a1v, vv, ww)                                                   \
    m = __byte_perm((uint32_t)(a0v), (uint32_t)(a1v), 0x5410) * 0x3F80u;                 \
    dst = asu32(__hmul2(__hmax2(__hmul2(UX, asb2(vv)), __hmul2(UX2, asb2(ww))), asb2(m)));
    PV_PAIR(po[0], Ac[0].x, Ac[0].y, vA.x, wA.x)
    PV_PAIR(po[1], Ac[0].z, Ac[0].w, vA.y, wA.y)
    PV_PAIR(po[2], Ac[1].x, Ac[1].y, vA.z, wA.z)
    PV_PAIR(po[3], Ac[1].z, Ac[1].w, vA.w, wA.w)
    PV_PAIR(po[4], Ac[2].x, Ac[2].y, vB.x, wB.x)
    PV_PAIR(po[5], Ac[2].z, Ac[2].w, vB.y, wB.y)
    PV_PAIR(po[6], Ac[3].x, Ac[3].y, vB.z, wB.z)
    PV_PAIR(po[7], Ac[3].z, Ac[3].w, vB.w, wB.w)
#undef PV_PAIR
    char* pdst = smem + OFF_PT + buf * PT_STRIDE + il * 272 + (jc << 5);
    *(uint4*)pdst = make_uint4(po[0], po[1], po[2], po[3]);
    *(uint4*)(pdst + 16) = make_uint4(po[4], po[5], po[6], po[7]);
    float z = 0.f;
#pragma unroll
    for (int q = 0; q < 8; q++) {
        float2 f = __bfloat1622float2(asb2(po[q]));
        z += f.x + f.y;
    }
    return z;
}

__global__ __launch_bounds__(256, 4) void k_pv(const int* __restrict__ A) {
    extern __shared__ __align__(16) char smem[];
    uint32_t sm = (uint32_t)__cvta_generic_to_shared(smem);
    int tid = threadIdx.x, lane = tid & 31, wid = tid >> 5;
    int i0 = (blockIdx.x >> 2) * 32;
    int jq = blockIdx.x & 3;
    int jbase = jq * 2048;
    int mi = (wid >> 2) * 16, nb = (wid & 3) * 16;
    int il = tid >> 3, jc = tid & 7;
    const int4* arow = (const int4*)(A + (long)(i0 + il) * NN + jbase) + (jc << 2);
    __nv_bfloat162 UX = asb2(g_up[i0 + il]);
    __nv_bfloat162 UX2 = asb2(g_up2[i0 + il]);

    float acc[2][4];
#pragma unroll
    for (int j = 0; j < 4; j++) { acc[0][j] = 0.f; acc[1][j] = 0.f; }
    float zacc = 0.f;

    // prologue: gT0 in flight; build P0; A tile 1 into regs
    pv_load_gt(sm, 0, jbase, tid);
    int4 Ac[4];
#pragma unroll
    for (int q = 0; q < 4; q++) Ac[q] = __ldcs(arow + q);
    zacc += pv_build(smem, 0, jbase, Ac, UX, UX2, il, jc);
#pragma unroll
    for (int q = 0; q < 4; q++) Ac[q] = __ldcs(arow + 32 + q);

    int g = lane >> 3;
    int r = (lane & 7) + (g & 1) * 8;
    int c = (g >> 1) * 8;

    for (int jt = 0; jt < NJT; jt++) {
        __syncthreads();   // pT[jt&1] built; gT[(jt+1)&1] free (mma jt-1 done)

        if (jt < NJT - 1) {
            pv_load_gt(sm, (jt + 1) & 1, jbase + ((jt + 1) << 7), tid);
            asm volatile("cp.async.wait_group 1;" ::: "memory");
        } else {
            asm volatile("cp.async.wait_group 0;" ::: "memory");
        }

        const char* pb = smem + OFF_PT + (jt & 1) * PT_STRIDE;
        const char* hb = smem + OFF_GT + (jt & 1) * GT_STRIDE;
#pragma unroll
        for (int ks = 0; ks < 8; ks++) {
            uint32_t a0, a1, a2, a3;
            ldsm4(a0, a1, a2, a3, pb + (mi + r) * 272 + (ks * 16 + c) * 2);
            uint32_t b0, b1r, b2, b3;
            ldsm4t(b0, b1r, b2, b3, hb + (ks * 16 + r) * 144 + (nb + c) * 2);
            mma16816(acc[0], a0, a1, a2, a3, b0, b1r);
            mma16816(acc[1], a0, a1, a2, a3, b2, b3);
        }

        if (jt < NJT - 1) {
            zacc += pv_build(smem, (jt + 1) & 1, jbase + ((jt + 1) << 7), Ac, UX, UX2, il, jc);
            if (jt < NJT - 2) {
#pragma unroll
                for (int q = 0; q < 4; q++) Ac[q] = __ldcs(arow + (long)(jt + 2) * 32 + q);
            }
        }
    }

    // write fp32 numerator partials
    int r0 = mi + (lane >> 2);
    float* P0 = g_Part + ((size_t)jq * NN + (i0 + r0)) * PROW;
    float* P1 = P0 + 8 * PROW;
#pragma unroll
    for (int h = 0; h < 2; h++) {
        int cb = nb + h * 8 + (lane & 3) * 2;
        P0[cb] = acc[h][0];
        P0[cb + 1] = acc[h][1];
        P1[cb] = acc[h][2];
        P1[cb + 1] = acc[h][3];
    }
    // Z: reduce across the 8 lanes sharing row il (lanes form aligned groups of 8)
    zacc += __shfl_xor_sync(0xffffffffu, zacc, 4);
    zacc += __shfl_xor_sync(0xffffffffu, zacc, 2);
    zacc += __shfl_xor_sync(0xffffffffu, zacc, 1);
    if (jc == 0) g_Part[((size_t)jq * NN + (i0 + il)) * PROW + 64] = zacc;
}

// ---------------- k_fin: combine 4 split-j partials + sigmoid ----------------
__global__ void k_fin(const float* __restrict__ beta, float* __restrict__ out) {
    int idx = blockIdx.x * 256 + threadIdx.x;
    if (idx >= NN * OUTD) return;
    int rr = idx >> 6, cc = idx & 63;
    float n = 0.f, z = 0.f;
#pragma unroll
    for (int q = 0; q < 4; q++) {
        const float* p = g_Part + ((size_t)q * NN + rr) * PROW;
        n += p[cc];
        z += p[64];
    }
    out[idx] = 1.f / (1.f + expf(-(n / z + beta[cc])));
}

// ---------------- launch: k_pv at profiled index 3 ----------------
extern "C" void kernel_launch(void* const* d_in, const int* in_sizes, int n_in,
                              void* d_out, int out_size) {
    const float* X = (const float*)d_in[0];
    const int* A = (const int*)d_in[1];
    const float* W1 = (const float*)d_in[2];
    const float* b1 = (const float*)d_in[3];
    const float* a = (const float*)d_in[4];
    const float* Omega = (const float*)d_in[5];
    const float* beta = (const float*)d_in[6];
    float* out = (float*)d_out;

    cudaFuncSetAttribute(k_pv, cudaFuncAttributeMaxDynamicSharedMemorySize, SMEM_PV);

    k_prep<<<IND + 1, 128>>>(W1, b1, a, Omega);
    k_sg<<<NN / 64, 256>>>(X);
    k_maxuv<<<1, 1024>>>();
    k_pv<<<(NN / 32) * 4, 256, SMEM_PV>>>(A);
    k_fin<<<(NN * OUTD + 255) / 256, 256>>>(beta, out);
}

// round 16
// speedup vs baseline: 1.6148x; 1.3690x over previous
#include <cuda_runtime.h>
#include <cuda_bf16.h>
#include <cstdint>

#define NN 8192
#define IND 512
#define HID 256
#define OUTD 64
#define NC 80       // Wt cols: G[0:64], s1=64, s2=65, pad to 80
#define NJT 32      // j-tiles of 128 per CTA (split-j: 2 halves of 4096)
#define PROW 68     // partial row stride (floats): 64 cols + 4 Z partials

// ---------------- scratch ----------------
__device__ __nv_bfloat16 g_Wt[1024 * NC];   // split W-tilde, chunk-interleaved rows
__device__ float g_bc[66];
__device__ __nv_bfloat16 g_Gb[NN * OUTD];   // G = H1@Omega + b, bf16 row-major (L2-resident)
__device__ float g_s1[NN], g_s2[NN];
__device__ uint32_t g_up[NN], g_up2[NN];    // u_i / u2_i duplicated bf16x2
__device__ uint32_t g_vp[NN / 2], g_vp2[NN / 2];
__device__ float g_Part[2 * NN * PROW];     // split-j partials [jhalf][row][68]

// ---------------- mma helpers ----------------
__device__ __forceinline__ void ldsm4(uint32_t& r0, uint32_t& r1, uint32_t& r2, uint32_t& r3,
                                      const void* p) {
    uint32_t ad = (uint32_t)__cvta_generic_to_shared(p);
    asm volatile("ldmatrix.sync.aligned.m8n8.x4.shared.b16 {%0,%1,%2,%3}, [%4];"
                 : "=r"(r0), "=r"(r1), "=r"(r2), "=r"(r3) : "r"(ad));
}
__device__ __forceinline__ void ldsm4t(uint32_t& r0, uint32_t& r1, uint32_t& r2, uint32_t& r3,
                                       const void* p) {
    uint32_t ad = (uint32_t)__cvta_generic_to_shared(p);
    asm volatile("ldmatrix.sync.aligned.m8n8.x4.trans.shared.b16 {%0,%1,%2,%3}, [%4];"
                 : "=r"(r0), "=r"(r1), "=r"(r2), "=r"(r3) : "r"(ad));
}
__device__ __forceinline__ void mma16816(float* c, uint32_t a0, uint32_t a1, uint32_t a2,
                                         uint32_t a3, uint32_t b0, uint32_t b1) {
    asm volatile(
        "mma.sync.aligned.m16n8k16.row.col.f32.bf16.bf16.f32 "
        "{%0,%1,%2,%3}, {%4,%5,%6,%7}, {%8,%9}, {%0,%1,%2,%3};"
        : "+f"(c[0]), "+f"(c[1]), "+f"(c[2]), "+f"(c[3])
        : "r"(a0), "r"(a1), "r"(a2), "r"(a3), "r"(b0), "r"(b1));
}
__device__ __forceinline__ __nv_bfloat162 asb2(uint32_t x) {
    return *reinterpret_cast<__nv_bfloat162*>(&x);
}
__device__ __forceinline__ uint32_t asu32(__nv_bfloat162 x) {
    return *reinterpret_cast<uint32_t*>(&x);
}

// ---------------- k_prep: W~ = [W1@Omega | W1@a1 | W1@a2], chunk-interleaved split rows ----
__global__ void k_prep(const float* __restrict__ W1, const float* __restrict__ b1,
                       const float* __restrict__ a, const float* __restrict__ Omega) {
    __shared__ float wrow[HID];
    int blk = blockIdx.x;   // 0..511: W1 row; 512: b1
    int tid = threadIdx.x;
    const float* src = (blk < IND) ? (W1 + blk * HID) : b1;
    for (int k = tid; k < HID; k += 128) wrow[k] = src[k];
    __syncthreads();
    if (tid >= NC) return;
    float val = 0.f;
    if (tid < 64) {
        for (int k = 0; k < HID; k++) val += wrow[k] * Omega[k * OUTD + tid];
    } else if (tid == 64) {
        for (int k = 0; k < HID; k++) val += wrow[k] * a[k];
    } else if (tid == 65) {
        for (int k = 0; k < HID; k++) val += wrow[k] * a[HID + k];
    }
    if (blk < IND) {
        __nv_bfloat16 hi = __float2bfloat16(val);
        float lo = val - __bfloat162float(hi);
        int rhi = ((blk >> 5) << 6) + (blk & 31);
        g_Wt[rhi * NC + tid] = hi;
        g_Wt[(rhi + 32) * NC + tid] = __float2bfloat16(lo);
    } else if (tid < 66) {
        g_bc[tid] = val;
    }
}

// ---------------- k_sg: [G | s1 | s2] = split(X) @ Wt, inline fp32->bf16 hi/lo split ------
__global__ __launch_bounds__(256) void k_sg(const float* __restrict__ X) {
    __shared__ __align__(16) __nv_bfloat16 aT[64][72];   // 64 rows x (32 hi | 32 lo)
    __shared__ __align__(16) __nv_bfloat16 bT[64][88];
    int tid = threadIdx.x, lane = tid & 31, w = tid >> 5;
    int m0 = blockIdx.x * 64;
    int mi = (w >> 1) * 16;
    int cw = w & 1;   // 0: nt 0..2 (cols 0-47), 1: nt 3..4 (cols 48-79)
    float acc[6][4];
#pragma unroll
    for (int i = 0; i < 6; i++)
#pragma unroll
        for (int j = 0; j < 4; j++) acc[i][j] = 0.f;

    for (int ch = 0; ch < 16; ch++) {
#pragma unroll
        for (int q = 0; q < 2; q++) {
            int idx = q * 256 + tid;          // 512 float4
            int rr = idx >> 3, c4 = (idx & 7) * 4;
            float4 xv = *(const float4*)&X[(m0 + rr) * IND + ch * 32 + c4];
            __nv_bfloat162 h0 = __floats2bfloat162_rn(xv.x, xv.y);
            __nv_bfloat162 h1 = __floats2bfloat162_rn(xv.z, xv.w);
            __nv_bfloat162 l0 = __floats2bfloat162_rn(xv.x - __bfloat162float(__low2bfloat16(h0)),
                                                      xv.y - __bfloat162float(__high2bfloat16(h0)));
            __nv_bfloat162 l1 = __floats2bfloat162_rn(xv.z - __bfloat162float(__low2bfloat16(h1)),
                                                      xv.w - __bfloat162float(__high2bfloat16(h1)));
            *(uint2*)&aT[rr][c4] = make_uint2(asu32(h0), asu32(h1));
            *(uint2*)&aT[rr][32 + c4] = make_uint2(asu32(l0), asu32(l1));
        }
#pragma unroll
        for (int q = 0; q < 3; q++) {
            int idx = q * 256 + tid;
            if (idx < 640) {
                int rr = idx / 10, cc = idx % 10;
                *(uint4*)&bT[rr][cc * 8] = *(const uint4*)&g_Wt[(ch * 64 + rr) * NC + cc * 8];
            }
        }
        __syncthreads();
        int g = lane >> 3;
        int r = (lane & 7) + (g & 1) * 8;
        int c = (g >> 1) * 8;
#pragma unroll
        for (int ks = 0; ks < 64; ks += 16) {
            uint32_t a0, a1, a2, a3;
            ldsm4(a0, a1, a2, a3, &aT[mi + r][ks + c]);
            if (cw == 0) {
#pragma unroll
                for (int nt = 0; nt < 3; nt++) {
                    uint32_t b0, b1r, b2, b3;
                    ldsm4t(b0, b1r, b2, b3, &bT[ks + r][nt * 16 + c]);
                    mma16816(acc[nt * 2], a0, a1, a2, a3, b0, b1r);
                    mma16816(acc[nt * 2 + 1], a0, a1, a2, a3, b2, b3);
                }
            } else {
#pragma unroll
                for (int nt2 = 0; nt2 < 2; nt2++) {
                    uint32_t b0, b1r, b2, b3;
                    ldsm4t(b0, b1r, b2, b3, &bT[ks + r][(nt2 + 3) * 16 + c]);
                    mma16816(acc[nt2 * 2], a0, a1, a2, a3, b0, b1r);
                    mma16816(acc[nt2 * 2 + 1], a0, a1, a2, a3, b2, b3);
                }
            }
        }
        __syncthreads();
    }
    int r0 = m0 + mi + (lane >> 2);
    if (cw == 0) {
#pragma unroll
        for (int nt = 0; nt < 3; nt++)
#pragma unroll
            for (int h = 0; h < 2; h++) {
                int j = nt * 2 + h;
                int cb = nt * 16 + h * 8 + (lane & 3) * 2;
                float b0v = g_bc[cb], b1v = g_bc[cb + 1];
                __nv_bfloat162 p0 = __floats2bfloat162_rn(acc[j][0] + b0v, acc[j][1] + b1v);
                __nv_bfloat162 p1 = __floats2bfloat162_rn(acc[j][2] + b0v, acc[j][3] + b1v);
                *(uint32_t*)&g_Gb[r0 * OUTD + cb] = asu32(p0);
                *(uint32_t*)&g_Gb[(r0 + 8) * OUTD + cb] = asu32(p1);
            }
    } else {
#pragma unroll
        for (int h = 0; h < 2; h++) {
            int cb = 48 + h * 8 + (lane & 3) * 2;
            float b0v = g_bc[cb], b1v = g_bc[cb + 1];
            __nv_bfloat162 p0 = __floats2bfloat162_rn(acc[h][0] + b0v, acc[h][1] + b1v);
            __nv_bfloat162 p1 = __floats2bfloat162_rn(acc[h][2] + b0v, acc[h][3] + b1v);
            *(uint32_t*)&g_Gb[r0 * OUTD + cb] = asu32(p0);
            *(uint32_t*)&g_Gb[(r0 + 8) * OUTD + cb] = asu32(p1);
        }
        if ((lane & 3) == 0) {
            g_s1[r0] = acc[2][0] + g_bc[64];
            g_s2[r0] = acc[2][1] + g_bc[65];
            g_s1[r0 + 8] = acc[2][2] + g_bc[64];
            g_s2[r0 + 8] = acc[2][3] + g_bc[65];
        }
    }
}

// ---------------- k_maxuv: single-CTA max(s2) + u/v factor packing ----------------
__global__ __launch_bounds__(1024) void k_maxuv() {
    __shared__ float red[32];
    int tid = threadIdx.x, lane = tid & 31;
    float m = -1e30f;
    for (int i = tid; i < NN; i += 1024) m = fmaxf(m, g_s2[i]);
#pragma unroll
    for (int o = 16; o; o >>= 1) m = fmaxf(m, __shfl_xor_sync(0xffffffffu, m, o));
    if (lane == 0) red[tid >> 5] = m;
    __syncthreads();
    if (tid < 32) {
        float x = red[tid];
#pragma unroll
        for (int o = 16; o; o >>= 1) x = fmaxf(x, __shfl_xor_sync(0xffffffffu, x, o));
        if (tid == 0) red[0] = x;
    }
    __syncthreads();
    float M = red[0];
    for (int i = tid; i < NN; i += 1024) {
        float s1 = g_s1[i], s2 = g_s2[i];
        float t = s1 + M;
        float c = t > 0.f ? t : 0.2f * t;   // valid softmax shift (leaky_relu monotone)
        uint32_t ub = (uint32_t)__bfloat16_as_ushort(__float2bfloat16(expf(s1 - c)));
        g_up[i] = ub | (ub << 16);
        uint32_t u2b = (uint32_t)__bfloat16_as_ushort(__float2bfloat16(expf(0.2f * s1 - c)));
        g_up2[i] = u2b | (u2b << 16);
        if (i < NN / 2) {
            float sa = g_s2[2 * i], sb = g_s2[2 * i + 1];
            uint32_t v0 = (uint32_t)__bfloat16_as_ushort(__float2bfloat16(expf(sa)));
            uint32_t v1 = (uint32_t)__bfloat16_as_ushort(__float2bfloat16(expf(sb)));
            g_vp[i] = v0 | (v1 << 16);
            uint32_t w0 = (uint32_t)__bfloat16_as_ushort(__float2bfloat16(expf(0.2f * sa)));
            uint32_t w1 = (uint32_t)__bfloat16_as_ushort(__float2bfloat16(expf(0.2f * sb)));
            g_vp2[i] = w0 | (w1 << 16);
        }
    }
}

// ---------------- k_pv: partials = P@[G|1] (split-j, 512 CTAs, balanced Z mma) ----------
// smem: gT[2][128][72] bf16 (cp.async double buffer), pT[2][32][136] bf16
#define GT_STRIDE 18432                     // 128*144 B
#define OFF_GT 0                            // 2 * 18432 = 36864
#define OFF_PT 36864                        // 2 * 8704 = 17408
#define PT_STRIDE 8704                      // 32*272 B
#define SMEM_PV 54272

__device__ __forceinline__ void pv_load_gt(uint32_t sm, int buf, int j0, int tid) {
    uint32_t dbase = sm + OFF_GT + buf * GT_STRIDE;
    const char* src = (const char*)(g_Gb + (size_t)j0 * OUTD);
#pragma unroll
    for (int q = 0; q < 4; q++) {
        int idx = q * 256 + tid;
        int r = idx >> 3, cc = idx & 7;
        asm volatile("cp.async.cg.shared.global [%0], [%1], 16;" ::"r"(dbase + r * 144 + cc * 16),
                     "l"(src + r * 128 + cc * 16));
    }
    asm volatile("cp.async.commit_group;" ::: "memory");
}

__device__ __forceinline__ void pv_build(char* smem, int buf, int j0, const int4* Ac,
                                         __nv_bfloat162 UX, __nv_bfloat162 UX2, int il, int jc) {
    const uint4* vp = (const uint4*)(g_vp + (j0 >> 1) + (jc << 3));
    uint4 vA = __ldg(vp), vB = __ldg(vp + 1);
    const uint4* wp = (const uint4*)(g_vp2 + (j0 >> 1) + (jc << 3));
    uint4 wA = __ldg(wp), wB = __ldg(wp + 1);
    uint32_t po[8];
    uint32_t m;
#define PV_PAIR(dst, a0v, a1v, vv, ww)                                                   \
    m = __byte_perm((uint32_t)(a0v), (uint32_t)(a1v), 0x5410) * 0x3F80u;                 \
    dst = asu32(__hmul2(__hmax2(__hmul2(UX, asb2(vv)), __hmul2(UX2, asb2(ww))), asb2(m)));
    PV_PAIR(po[0], Ac[0].x, Ac[0].y, vA.x, wA.x)
    PV_PAIR(po[1], Ac[0].z, Ac[0].w, vA.y, wA.y)
    PV_PAIR(po[2], Ac[1].x, Ac[1].y, vA.z, wA.z)
    PV_PAIR(po[3], Ac[1].z, Ac[1].w, vA.w, wA.w)
    PV_PAIR(po[4], Ac[2].x, Ac[2].y, vB.x, wB.x)
    PV_PAIR(po[5], Ac[2].z, Ac[2].w, vB.y, wB.y)
    PV_PAIR(po[6], Ac[3].x, Ac[3].y, vB.z, wB.z)
    PV_PAIR(po[7], Ac[3].z, Ac[3].w, vB.w, wB.w)
#undef PV_PAIR
    char* pdst = smem + OFF_PT + buf * PT_STRIDE + il * 272 + (jc << 5);
    *(uint4*)pdst = make_uint4(po[0], po[1], po[2], po[3]);
    *(uint4*)(pdst + 16) = make_uint4(po[4], po[5], po[6], po[7]);
}

__global__ __launch_bounds__(256, 4) void k_pv(const int* __restrict__ A) {
    extern __shared__ __align__(16) char smem[];
    uint32_t sm = (uint32_t)__cvta_generic_to_shared(smem);
    int tid = threadIdx.x, lane = tid & 31, wid = tid >> 5;
    int i0 = (blockIdx.x >> 1) * 32;
    int jhalf = blockIdx.x & 1;
    int jbase = jhalf * 4096;
    int mi = (wid >> 2) * 16, nb = (wid & 3) * 16;
    int cwid = wid & 3;                     // column-warp id: Z round-robin key
    int il = tid >> 3, jc = tid & 7;
    const int4* arow = (const int4*)(A + (long)(i0 + il) * NN + jbase) + (jc << 2);
    __nv_bfloat162 UX = asb2(g_up[i0 + il]);
    __nv_bfloat162 UX2 = asb2(g_up2[i0 + il]);

    float acc[2][4], accz[4];
#pragma unroll
    for (int j = 0; j < 4; j++) { acc[0][j] = 0.f; acc[1][j] = 0.f; accz[j] = 0.f; }

    // prologue: gT0 in flight; build P0; A tile 1 into regs
    pv_load_gt(sm, 0, jbase, tid);
    int4 Ac[4];
#pragma unroll
    for (int q = 0; q < 4; q++) Ac[q] = __ldcs(arow + q);
    pv_build(smem, 0, jbase, Ac, UX, UX2, il, jc);
#pragma unroll
    for (int q = 0; q < 4; q++) Ac[q] = __ldcs(arow + 32 + q);

    const uint32_t ONES = 0x3F803F80u;
    int g = lane >> 3;
    int r = (lane & 7) + (g & 1) * 8;
    int c = (g >> 1) * 8;

    for (int jt = 0; jt < NJT; jt++) {
        __syncthreads();   // pT[jt&1] built; gT[(jt+1)&1] free (mma jt-1 done)

        if (jt < NJT - 1) {
            pv_load_gt(sm, (jt + 1) & 1, jbase + ((jt + 1) << 7), tid);
            asm volatile("cp.async.wait_group 1;" ::: "memory");
        } else {
            asm volatile("cp.async.wait_group 0;" ::: "memory");
        }

        const char* pb = smem + OFF_PT + (jt & 1) * PT_STRIDE;
        const char* hb = smem + OFF_GT + (jt & 1) * GT_STRIDE;
#pragma unroll
        for (int ks = 0; ks < 8; ks++) {
            uint32_t a0, a1, a2, a3;
            ldsm4(a0, a1, a2, a3, pb + (mi + r) * 272 + (ks * 16 + c) * 2);
            // Z ones-mma distributed round-robin over ks across the 4 col-warps:
            // every warp does exactly 2 Z-mma per jt -> uniform 18 mma/warp/jt.
            if ((ks & 3) == cwid) mma16816(accz, a0, a1, a2, a3, ONES, ONES);
            uint32_t b0, b1r, b2, b3;
            ldsm4t(b0, b1r, b2, b3, hb + (ks * 16 + r) * 144 + (nb + c) * 2);
            mma16816(acc[0], a0, a1, a2, a3, b0, b1r);
            mma16816(acc[1], a0, a1, a2, a3, b2, b3);
        }

        if (jt < NJT - 1) {
            pv_build(smem, (jt + 1) & 1, jbase + ((jt + 1) << 7), Ac, UX, UX2, il, jc);
            if (jt < NJT - 2) {
#pragma unroll
                for (int q = 0; q < 4; q++) Ac[q] = __ldcs(arow + (long)(jt + 2) * 32 + q);
            }
        }
    }

    // write fp32 partials (numerator + per-col-warp Z partials)
    int r0 = mi + (lane >> 2);
    float* P0 = g_Part + ((size_t)jhalf * NN + (i0 + r0)) * PROW;
    float* P1 = P0 + 8 * PROW;
#pragma unroll
    for (int h = 0; h < 2; h++) {
        int cb = nb + h * 8 + (lane & 3) * 2;
        P0[cb] = acc[h][0];
        P0[cb + 1] = acc[h][1];
        P1[cb] = acc[h][2];
        P1[cb + 1] = acc[h][3];
    }
    if ((lane & 3) == 0) {
        P0[64 + cwid] = accz[0];
        P1[64 + cwid] = accz[2];
    }
}

// ---------------- k_fin: combine split-j partials (+4-way Z) + sigmoid ----------------
__global__ void k_fin(const float* __restrict__ beta, float* __restrict__ out) {
    int idx = blockIdx.x * 256 + threadIdx.x;
    if (idx >= NN * OUTD) return;
    int rr = idx >> 6, cc = idx & 63;
    float n = 0.f, z = 0.f;
#pragma unroll
    for (int q = 0; q < 2; q++) {
        const float* p = g_Part + ((size_t)q * NN + rr) * PROW;
        n += p[cc];
        z += (p[64] + p[65]) + (p[66] + p[67]);
    }
    out[idx] = 1.f / (1.f + expf(-(n / z + beta[cc])));
}

// ---------------- launch: k_pv at profiled index 3 ----------------
extern "C" void kernel_launch(void* const* d_in, const int* in_sizes, int n_in,
                              void* d_out, int out_size) {
    const float* X = (const float*)d_in[0];
    const int* A = (const int*)d_in[1];
    const float* W1 = (const float*)d_in[2];
    const float* b1 = (const float*)d_in[3];
    const float* a = (const float*)d_in[4];
    const float* Omega = (const float*)d_in[5];
    const float* beta = (const float*)d_in[6];
    float* out = (float*)d_out;

    cudaFuncSetAttribute(k_pv, cudaFuncAttributeMaxDynamicSharedMemorySize, SMEM_PV);

    k_prep<<<IND + 1, 128>>>(W1, b1, a, Omega);
    k_sg<<<NN / 64, 256>>>(X);
    k_maxuv<<<1, 1024>>>();
    k_pv<<<(NN / 32) * 2, 256, SMEM_PV>>>(A);
    k_fin<<<(NN * OUTD + 255) / 256, 256>>>(beta, out);
}